// round 1
// baseline (speedup 1.0000x reference)
#include <cuda_runtime.h>
#include <cuda_bf16.h>
#include <cstdint>

#define TB 4
#define TS 4096
#define TH 1024
#define TE 8
#define TD 256
#define TT (TB*TS)   // 16384 tokens

// -------- device scratch (static, no allocations) --------
__device__ int   g_expert_of[TT];
__device__ int   g_count[TE];
__device__ int   g_offset[TE+1];
__device__ int   g_cursor[TE];
__device__ int   g_token_list[TT];
__device__ float g_inter[(size_t)TT*TD];   // 16MB, permuted-order rows

// -------- kernel 0: zero counts --------
__global__ void k_zero() {
    int i = threadIdx.x;
    if (i < TE) { g_count[i] = 0; g_cursor[i] = 0; }
}

// -------- kernel 1: router (one warp per token) --------
__global__ void k_router(const float* __restrict__ x, const float* __restrict__ gw) {
    __shared__ float sgw[TE*TH];           // 32KB
    for (int i = threadIdx.x; i < TE*TH; i += blockDim.x) sgw[i] = gw[i];
    __syncthreads();
    int warp = threadIdx.x >> 5, lane = threadIdx.x & 31;
    int t = blockIdx.x * 8 + warp;
    if (t >= TT) return;
    const float* xr = x + (size_t)t * TH;
    float acc[TE];
    #pragma unroll
    for (int e = 0; e < TE; e++) acc[e] = 0.f;
    #pragma unroll 4
    for (int i = 0; i < TH/32; i++) {
        float xv = xr[i*32 + lane];
        #pragma unroll
        for (int e = 0; e < TE; e++) acc[e] += xv * sgw[e*TH + i*32 + lane];
    }
    #pragma unroll
    for (int off = 16; off; off >>= 1) {
        #pragma unroll
        for (int e = 0; e < TE; e++) acc[e] += __shfl_xor_sync(0xFFFFFFFFu, acc[e], off);
    }
    if (lane == 0) {
        int best = 0; float bv = acc[0];
        #pragma unroll
        for (int e = 1; e < TE; e++) if (acc[e] > bv) { bv = acc[e]; best = e; }  // first-max tie rule
        g_expert_of[t] = best;
        atomicAdd(&g_count[best], 1);
    }
}

// -------- kernel 2: scan --------
__global__ void k_scan() {
    if (threadIdx.x == 0) {
        int s = 0;
        for (int e = 0; e < TE; e++) { g_offset[e] = s; s += g_count[e]; }
        g_offset[TE] = s;
    }
}

// -------- kernel 3: scatter tokens into expert buckets --------
__global__ void k_scatter() {
    int t = blockIdx.x * blockDim.x + threadIdx.x;
    if (t < TT) {
        int e = g_expert_of[t];
        int p = g_offset[e] + atomicAdd(&g_cursor[e], 1);
        g_token_list[p] = t;
    }
}

// -------- kernel 4: fused up+gate GEMM + relu^2*u epilogue --------
// inter[p, :] = relu(x[tok]·wg[e])^2 * (x[tok]·wu[e]),   p = permuted position
// BM=64 BN=64 BK=16, 256 threads, 4x4 per thread, dual accumulators
__global__ __launch_bounds__(256) void k_upgate(const float* __restrict__ x,
                                                const float* __restrict__ wg,
                                                const float* __restrict__ wu) {
    const int e   = blockIdx.z;
    const int off = g_offset[e];
    const int cnt = g_offset[e+1] - off;
    const int m0  = blockIdx.x * 64;
    if (m0 >= cnt) return;
    const int n0  = blockIdx.y * 64;

    __shared__ float As[16][65];
    __shared__ float Bg[16][64];
    __shared__ float Bu[16][64];
    __shared__ int   rows[64];

    const int tid = threadIdx.x;
    if (tid < 64) {
        int m = m0 + tid;
        rows[tid] = (m < cnt) ? g_token_list[off + m] : -1;
    }
    __syncthreads();

    const float* wge = wg + (size_t)e * TH * TD;
    const float* wue = wu + (size_t)e * TH * TD;

    const int la_r = tid >> 2;            // 0..63
    const int la_k = (tid & 3) * 4;       // 0..12
    const int lb_k = tid >> 4;            // 0..15
    const int lb_n = (tid & 15) * 4;      // 0..60
    const int tx = tid & 15, ty = tid >> 4;
    const int a_tok = rows[la_r];

    float accG[4][4], accU[4][4];
    #pragma unroll
    for (int i = 0; i < 4; i++)
        #pragma unroll
        for (int j = 0; j < 4; j++) { accG[i][j] = 0.f; accU[i][j] = 0.f; }

    for (int k0 = 0; k0 < TH; k0 += 16) {
        float4 av = make_float4(0.f,0.f,0.f,0.f);
        if (a_tok >= 0) av = *(const float4*)(x + (size_t)a_tok*TH + k0 + la_k);
        As[la_k+0][la_r] = av.x; As[la_k+1][la_r] = av.y;
        As[la_k+2][la_r] = av.z; As[la_k+3][la_r] = av.w;
        *(float4*)&Bg[lb_k][lb_n] = *(const float4*)(wge + (size_t)(k0+lb_k)*TD + n0 + lb_n);
        *(float4*)&Bu[lb_k][lb_n] = *(const float4*)(wue + (size_t)(k0+lb_k)*TD + n0 + lb_n);
        __syncthreads();
        #pragma unroll
        for (int kk = 0; kk < 16; kk++) {
            float a[4], bg[4], bu[4];
            #pragma unroll
            for (int i = 0; i < 4; i++) a[i]  = As[kk][ty*4+i];
            #pragma unroll
            for (int j = 0; j < 4; j++) { bg[j] = Bg[kk][tx*4+j]; bu[j] = Bu[kk][tx*4+j]; }
            #pragma unroll
            for (int i = 0; i < 4; i++)
                #pragma unroll
                for (int j = 0; j < 4; j++) {
                    accG[i][j] += a[i] * bg[j];
                    accU[i][j] += a[i] * bu[j];
                }
        }
        __syncthreads();
    }

    #pragma unroll
    for (int i = 0; i < 4; i++) {
        int m = m0 + ty*4 + i;
        if (m < cnt) {
            float4 v;
            float gg;
            gg = fmaxf(accG[i][0], 0.f); v.x = gg*gg*accU[i][0];
            gg = fmaxf(accG[i][1], 0.f); v.y = gg*gg*accU[i][1];
            gg = fmaxf(accG[i][2], 0.f); v.z = gg*gg*accU[i][2];
            gg = fmaxf(accG[i][3], 0.f); v.w = gg*gg*accU[i][3];
            *(float4*)&g_inter[(size_t)(off + m)*TD + n0 + tx*4] = v;
        }
    }
}

// -------- kernel 5: down projection with scatter store --------
// out[token, :] = inter[p, :] · wd[e]   (K=256)
__global__ __launch_bounds__(256) void k_down(const float* __restrict__ wd,
                                              float* __restrict__ out) {
    const int e   = blockIdx.z;
    const int off = g_offset[e];
    const int cnt = g_offset[e+1] - off;
    const int m0  = blockIdx.x * 64;
    if (m0 >= cnt) return;
    const int n0  = blockIdx.y * 64;

    __shared__ float As[16][65];
    __shared__ float Bs[16][64];
    __shared__ int   rows[64];

    const int tid = threadIdx.x;
    if (tid < 64) {
        int m = m0 + tid;
        rows[tid] = (m < cnt) ? g_token_list[off + m] : -1;
    }
    __syncthreads();

    const float* wde = wd + (size_t)e * TD * TH;

    const int la_r = tid >> 2;
    const int la_k = (tid & 3) * 4;
    const int lb_k = tid >> 4;
    const int lb_n = (tid & 15) * 4;
    const int tx = tid & 15, ty = tid >> 4;
    const bool a_ok = (m0 + la_r) < cnt;
    const size_t a_row = (size_t)(off + m0 + la_r) * TD;

    float acc[4][4];
    #pragma unroll
    for (int i = 0; i < 4; i++)
        #pragma unroll
        for (int j = 0; j < 4; j++) acc[i][j] = 0.f;

    for (int k0 = 0; k0 < TD; k0 += 16) {
        float4 av = make_float4(0.f,0.f,0.f,0.f);
        if (a_ok) av = *(const float4*)(g_inter + a_row + k0 + la_k);
        As[la_k+0][la_r] = av.x; As[la_k+1][la_r] = av.y;
        As[la_k+2][la_r] = av.z; As[la_k+3][la_r] = av.w;
        *(float4*)&Bs[lb_k][lb_n] = *(const float4*)(wde + (size_t)(k0+lb_k)*TH + n0 + lb_n);
        __syncthreads();
        #pragma unroll
        for (int kk = 0; kk < 16; kk++) {
            float a[4], b[4];
            #pragma unroll
            for (int i = 0; i < 4; i++) a[i] = As[kk][ty*4+i];
            #pragma unroll
            for (int j = 0; j < 4; j++) b[j] = Bs[kk][tx*4+j];
            #pragma unroll
            for (int i = 0; i < 4; i++)
                #pragma unroll
                for (int j = 0; j < 4; j++) acc[i][j] += a[i]*b[j];
        }
        __syncthreads();
    }

    #pragma unroll
    for (int i = 0; i < 4; i++) {
        int tok = rows[ty*4 + i];
        if (tok >= 0) {
            float4 v = make_float4(acc[i][0], acc[i][1], acc[i][2], acc[i][3]);
            *(float4*)(out + (size_t)tok*TH + n0 + tx*4) = v;
        }
    }
}

// -------- launch --------
extern "C" void kernel_launch(void* const* d_in, const int* in_sizes, int n_in,
                              void* d_out, int out_size) {
    const float* x  = (const float*)d_in[0];   // [B,S,H]
    const float* gw = (const float*)d_in[1];   // [E,H]
    const float* wg = (const float*)d_in[2];   // [E,H,D]
    const float* wu = (const float*)d_in[3];   // [E,H,D]
    const float* wd = (const float*)d_in[4];   // [E,D,H]
    float* out = (float*)d_out;

    k_zero<<<1, 32>>>();
    k_router<<<TT/8, 256>>>(x, gw);
    k_scan<<<1, 32>>>();
    k_scatter<<<TT/256, 256>>>();
    {
        dim3 grid(TT/64, TD/64, TE);   // (256, 4, 8); idle tiles exit on count check
        k_upgate<<<grid, 256>>>(x, wg, wu);
    }
    {
        dim3 grid(TT/64, TH/64, TE);   // (256, 16, 8)
        k_down<<<grid, 256>>>(wd, out);
    }
}

// round 10
// speedup vs baseline: 1.7397x; 1.7397x over previous
#include <cuda_runtime.h>
#include <cuda_bf16.h>
#include <cstdint>

#define TB 4
#define TS 4096
#define TH 1024
#define TE 8
#define TD 256
#define TT (TB*TS)   // 16384 tokens

// ================= device scratch (static; same set that passed in R1, fp32 only) =====
__device__ __align__(16) int   g_expert_of[TT];
__device__ __align__(16) int   g_count[TE];
__device__ __align__(16) int   g_offset[TE+1];
__device__ __align__(16) int   g_cursor[TE];
__device__ __align__(16) int   g_token_list[TT];
__device__ __align__(16) float g_inter[(size_t)TT*TD];   // 16MB, permuted-order rows, fp32

// ================= helpers =================
__device__ __forceinline__ void mma_bf16(float* c, const uint32_t* a, const uint32_t* b) {
    asm volatile("mma.sync.aligned.m16n8k16.row.col.f32.bf16.bf16.f32 "
                 "{%0,%1,%2,%3}, {%4,%5,%6,%7}, {%8,%9}, {%0,%1,%2,%3};"
                 : "+f"(c[0]), "+f"(c[1]), "+f"(c[2]), "+f"(c[3])
                 : "r"(a[0]), "r"(a[1]), "r"(a[2]), "r"(a[3]), "r"(b[0]), "r"(b[1]));
}
__device__ __forceinline__ void split_bf16(float v, __nv_bfloat16& h, __nv_bfloat16& l) {
    h = __float2bfloat16_rn(v);
    l = __float2bfloat16_rn(v - __bfloat162float(h));
}
#define RPAD 40   // bf16 elems per SMEM row (80B) -> conflict-free fragment LDS

// ================= kernel 0: zero =================
__global__ void k_zero() {
    int i = threadIdx.x;
    if (i < TE) { g_count[i] = 0; g_cursor[i] = 0; }
}

// ================= kernel 1: router =================
__global__ void k_router(const float* __restrict__ x, const float* __restrict__ gw) {
    __shared__ float sgw[TE*TH];
    for (int i = threadIdx.x; i < TE*TH; i += blockDim.x) sgw[i] = gw[i];
    __syncthreads();
    int warp = threadIdx.x >> 5, lane = threadIdx.x & 31;
    int t = blockIdx.x * 8 + warp;
    if (t >= TT) return;
    const float* xr = x + (size_t)t * TH;
    float acc[TE];
#pragma unroll
    for (int e = 0; e < TE; e++) acc[e] = 0.f;
#pragma unroll 4
    for (int i = 0; i < TH/32; i++) {
        float xv = xr[i*32 + lane];
#pragma unroll
        for (int e = 0; e < TE; e++) acc[e] += xv * sgw[e*TH + i*32 + lane];
    }
#pragma unroll
    for (int off = 16; off; off >>= 1)
#pragma unroll
        for (int e = 0; e < TE; e++) acc[e] += __shfl_xor_sync(0xFFFFFFFFu, acc[e], off);
    if (lane == 0) {
        int best = 0; float bv = acc[0];
#pragma unroll
        for (int e = 1; e < TE; e++) if (acc[e] > bv) { bv = acc[e]; best = e; }
        g_expert_of[t] = best;
        atomicAdd(&g_count[best], 1);
    }
}

// ================= kernel 2: scan =================
__global__ void k_scan() {
    if (threadIdx.x == 0) {
        int s = 0;
        for (int e = 0; e < TE; e++) { g_offset[e] = s; s += g_count[e]; }
        g_offset[TE] = s;
    }
}

// ================= kernel 3: scatter =================
__global__ void k_scatter() {
    int t = blockIdx.x * blockDim.x + threadIdx.x;
    if (t < TT) {
        int e = g_expert_of[t];
        int p = g_offset[e] + atomicAdd(&g_cursor[e], 1);
        g_token_list[p] = t;
    }
}

// ================= kernel 4: up+gate HMMA GEMM, fp32 in, in-kernel bf16 split =========
// CTA 128M x 64N, BK=32, K=1024 (32 chunks). 8 warps: wm=wid&3 (32 rows), wn=wid>>2 (32 cols).
// A: gathered x rows (fp32) -> hi/lo bf16 SMEM [row][k].
// B: wg/wu [K][N] fp32 -> transposed on store -> hi/lo SMEM [n][k].
#define SA_HI 0
#define SA_LO (128*RPAD)
#define SBGH  (2*128*RPAD)
#define SBGL  (2*128*RPAD + 64*RPAD)
#define SBUH  (2*128*RPAD + 2*64*RPAD)
#define SBUL  (2*128*RPAD + 3*64*RPAD)
#define G1_ELEMS (2*128*RPAD + 4*64*RPAD)
__global__ __launch_bounds__(256) void k_upgate_mma(const float* __restrict__ x,
                                                    const float* __restrict__ wg,
                                                    const float* __restrict__ wu) {
    __shared__ __align__(16) __nv_bfloat16 sm[G1_ELEMS];
    __shared__ int rowsS[128];
    const int tid = threadIdx.x, wid = tid >> 5, lane = tid & 31;
    const int e = blockIdx.z;
    const int off = g_offset[e];
    const int cnt = g_offset[e+1] - off;
    const int m0 = blockIdx.x * 128;
    if (m0 >= cnt) return;
    const int n0 = blockIdx.y * 64;
    const int valid = (cnt - m0 < 128) ? (cnt - m0) : 128;

    if (tid < 128) {
        int m = m0 + tid;
        rowsS[tid] = (m < cnt) ? g_token_list[off + m] : -1;
    }
    __syncthreads();

    const float* wge = wg + (size_t)e * TH * TD;
    const float* wue = wu + (size_t)e * TH * TD;

    // A loader: thread -> (row, half): 16 consecutive k each
    const int arow = tid >> 1, ahalf = tid & 1;
    int tokA = rowsS[arow];
    if (tokA < 0) tokA = rowsS[0];
    const float* asrc = x + (size_t)tokA * TH + ahalf * 16;
    // B loader: thread -> (n, 8 k values)
    const int bn = tid & 63, bk8 = (tid >> 6) * 8;

    float cG[2][4][4], cU[2][4][4];
#pragma unroll
    for (int a = 0; a < 2; a++)
#pragma unroll
        for (int b = 0; b < 4; b++)
#pragma unroll
            for (int c = 0; c < 4; c++) { cG[a][b][c] = 0.f; cU[a][b][c] = 0.f; }

    const int wm = wid & 3, wn = wid >> 2;
    const int qrow = lane >> 2, qk = (lane & 3) * 2;

    const int NC = TH / 32;   // 32
    for (int c = 0; c < NC; c++) {
        int k0 = c * 32;
        // ---- A: 16 fp32 -> 16 hi + 16 lo bf16 ----
        {
            __align__(16) __nv_bfloat16 hb[16], lb[16];
#pragma unroll
            for (int j = 0; j < 4; j++) {
                float4 v = *(const float4*)(asrc + k0 + j*4);
                split_bf16(v.x, hb[j*4+0], lb[j*4+0]);
                split_bf16(v.y, hb[j*4+1], lb[j*4+1]);
                split_bf16(v.z, hb[j*4+2], lb[j*4+2]);
                split_bf16(v.w, hb[j*4+3], lb[j*4+3]);
            }
            uint32_t ao = arow*RPAD + ahalf*16;
            *(uint4*)(sm + SA_HI + ao)     = ((uint4*)hb)[0];
            *(uint4*)(sm + SA_HI + ao + 8) = ((uint4*)hb)[1];
            *(uint4*)(sm + SA_LO + ao)     = ((uint4*)lb)[0];
            *(uint4*)(sm + SA_LO + ao + 8) = ((uint4*)lb)[1];
        }
        // ---- B (gate + up): 8 fp32 each along k (coalesced along n), transpose-store ----
        {
            __align__(16) __nv_bfloat16 hb[8], lb[8];
#pragma unroll
            for (int j = 0; j < 8; j++) {
                float v = wge[(size_t)(k0 + bk8 + j) * TD + n0 + bn];
                split_bf16(v, hb[j], lb[j]);
            }
            *(uint4*)(sm + SBGH + bn*RPAD + bk8) = *(uint4*)hb;
            *(uint4*)(sm + SBGL + bn*RPAD + bk8) = *(uint4*)lb;
#pragma unroll
            for (int j = 0; j < 8; j++) {
                float v = wue[(size_t)(k0 + bk8 + j) * TD + n0 + bn];
                split_bf16(v, hb[j], lb[j]);
            }
            *(uint4*)(sm + SBUH + bn*RPAD + bk8) = *(uint4*)hb;
            *(uint4*)(sm + SBUL + bn*RPAD + bk8) = *(uint4*)lb;
        }
        __syncthreads();
        // ---- compute: 2 k-steps of 16 ----
#pragma unroll
        for (int ks = 0; ks < 2; ks++) {
            uint32_t bGh[8], bGl[8], bUh[8], bUl[8];
#pragma unroll
            for (int nt = 0; nt < 4; nt++) {
                int boff = (wn*32 + nt*8 + qrow)*RPAD + ks*16 + qk;
                bGh[nt*2+0] = *(const uint32_t*)(sm + SBGH + boff);
                bGh[nt*2+1] = *(const uint32_t*)(sm + SBGH + boff + 8);
                bGl[nt*2+0] = *(const uint32_t*)(sm + SBGL + boff);
                bGl[nt*2+1] = *(const uint32_t*)(sm + SBGL + boff + 8);
                bUh[nt*2+0] = *(const uint32_t*)(sm + SBUH + boff);
                bUh[nt*2+1] = *(const uint32_t*)(sm + SBUH + boff + 8);
                bUl[nt*2+0] = *(const uint32_t*)(sm + SBUL + boff);
                bUl[nt*2+1] = *(const uint32_t*)(sm + SBUL + boff + 8);
            }
#pragma unroll
            for (int mt = 0; mt < 2; mt++) {
                int aoff = (wm*32 + mt*16 + qrow)*RPAD + ks*16 + qk;
                uint32_t aH[4], aL[4];
                aH[0] = *(const uint32_t*)(sm + SA_HI + aoff);
                aH[1] = *(const uint32_t*)(sm + SA_HI + aoff + 8*RPAD);
                aH[2] = *(const uint32_t*)(sm + SA_HI + aoff + 8);
                aH[3] = *(const uint32_t*)(sm + SA_HI + aoff + 8*RPAD + 8);
                aL[0] = *(const uint32_t*)(sm + SA_LO + aoff);
                aL[1] = *(const uint32_t*)(sm + SA_LO + aoff + 8*RPAD);
                aL[2] = *(const uint32_t*)(sm + SA_LO + aoff + 8);
                aL[3] = *(const uint32_t*)(sm + SA_LO + aoff + 8*RPAD + 8);
#pragma unroll
                for (int nt = 0; nt < 4; nt++) {
                    mma_bf16(cG[mt][nt], aH, &bGh[nt*2]);
                    mma_bf16(cG[mt][nt], aH, &bGl[nt*2]);
                    mma_bf16(cG[mt][nt], aL, &bGh[nt*2]);
                    mma_bf16(cU[mt][nt], aH, &bUh[nt*2]);
                    mma_bf16(cU[mt][nt], aH, &bUl[nt*2]);
                    mma_bf16(cU[mt][nt], aL, &bUh[nt*2]);
                }
            }
        }
        __syncthreads();
    }

    // epilogue: inter = relu(g)^2 * u, fp32 store to permuted rows
    const int qcol = (lane & 3) * 2;
#pragma unroll
    for (int mt = 0; mt < 2; mt++)
#pragma unroll
        for (int h = 0; h < 2; h++) {
            int rr = wm*32 + mt*16 + qrow + h*8;
            if (rr < valid) {
                float* rowp = g_inter + (size_t)(off + m0 + rr) * TD + n0;
#pragma unroll
                for (int nt = 0; nt < 4; nt++) {
                    float g0 = fmaxf(cG[mt][nt][h*2+0], 0.f);
                    float g1 = fmaxf(cG[mt][nt][h*2+1], 0.f);
                    float2 v = make_float2(g0*g0*cU[mt][nt][h*2+0],
                                           g1*g1*cU[mt][nt][h*2+1]);
                    *(float2*)(rowp + wn*32 + nt*8 + qcol) = v;
                }
            }
        }
}

// ================= kernel 5: down-proj HMMA GEMM + scatter store =================
// CTA 128M x 64N, BK=32, K=256 (8 chunks). A = g_inter fp32, B = wd [K=256][N=1024] fp32.
#define D_SA_HI 0
#define D_SA_LO (128*RPAD)
#define D_SBH   (2*128*RPAD)
#define D_SBL   (2*128*RPAD + 64*RPAD)
#define G2_ELEMS (2*128*RPAD + 2*64*RPAD)
__global__ __launch_bounds__(256) void k_down_mma(const float* __restrict__ wd,
                                                  float* __restrict__ out) {
    __shared__ __align__(16) __nv_bfloat16 sm[G2_ELEMS];
    __shared__ int rowsS[128];
    const int tid = threadIdx.x, wid = tid >> 5, lane = tid & 31;
    const int e = blockIdx.z;
    const int off = g_offset[e];
    const int cnt = g_offset[e+1] - off;
    const int m0 = blockIdx.x * 128;
    if (m0 >= cnt) return;
    const int n0 = blockIdx.y * 64;
    const int valid = (cnt - m0 < 128) ? (cnt - m0) : 128;

    if (tid < 128) {
        int m = m0 + tid;
        rowsS[tid] = (m < cnt) ? g_token_list[off + m] : -1;
    }
    __syncthreads();

    const float* wde = wd + (size_t)e * TD * TH;

    const int arow = tid >> 1, ahalf = tid & 1;
    const int arowc = (arow < valid) ? arow : (valid - 1);
    const float* asrc = g_inter + (size_t)(off + m0 + arowc) * TD + ahalf * 16;
    const int bn = tid & 63, bk8 = (tid >> 6) * 8;

    float cc[2][4][4];
#pragma unroll
    for (int a = 0; a < 2; a++)
#pragma unroll
        for (int b = 0; b < 4; b++)
#pragma unroll
            for (int c = 0; c < 4; c++) cc[a][b][c] = 0.f;

    const int wm = wid & 3, wn = wid >> 2;
    const int qrow = lane >> 2, qk = (lane & 3) * 2;

    const int NC = TD / 32;   // 8
    for (int c = 0; c < NC; c++) {
        int k0 = c * 32;
        {
            __align__(16) __nv_bfloat16 hb[16], lb[16];
#pragma unroll
            for (int j = 0; j < 4; j++) {
                float4 v = *(const float4*)(asrc + k0 + j*4);
                split_bf16(v.x, hb[j*4+0], lb[j*4+0]);
                split_bf16(v.y, hb[j*4+1], lb[j*4+1]);
                split_bf16(v.z, hb[j*4+2], lb[j*4+2]);
                split_bf16(v.w, hb[j*4+3], lb[j*4+3]);
            }
            uint32_t ao = arow*RPAD + ahalf*16;
            *(uint4*)(sm + D_SA_HI + ao)     = ((uint4*)hb)[0];
            *(uint4*)(sm + D_SA_HI + ao + 8) = ((uint4*)hb)[1];
            *(uint4*)(sm + D_SA_LO + ao)     = ((uint4*)lb)[0];
            *(uint4*)(sm + D_SA_LO + ao + 8) = ((uint4*)lb)[1];
        }
        {
            __align__(16) __nv_bfloat16 hb[8], lb[8];
#pragma unroll
            for (int j = 0; j < 8; j++) {
                float v = wde[(size_t)(k0 + bk8 + j) * TH + n0 + bn];
                split_bf16(v, hb[j], lb[j]);
            }
            *(uint4*)(sm + D_SBH + bn*RPAD + bk8) = *(uint4*)hb;
            *(uint4*)(sm + D_SBL + bn*RPAD + bk8) = *(uint4*)lb;
        }
        __syncthreads();
#pragma unroll
        for (int ks = 0; ks < 2; ks++) {
            uint32_t bH[8], bL[8];
#pragma unroll
            for (int nt = 0; nt < 4; nt++) {
                int boff = (wn*32 + nt*8 + qrow)*RPAD + ks*16 + qk;
                bH[nt*2+0] = *(const uint32_t*)(sm + D_SBH + boff);
                bH[nt*2+1] = *(const uint32_t*)(sm + D_SBH + boff + 8);
                bL[nt*2+0] = *(const uint32_t*)(sm + D_SBL + boff);
                bL[nt*2+1] = *(const uint32_t*)(sm + D_SBL + boff + 8);
            }
#pragma unroll
            for (int mt = 0; mt < 2; mt++) {
                int aoff = (wm*32 + mt*16 + qrow)*RPAD + ks*16 + qk;
                uint32_t aH[4], aL[4];
                aH[0] = *(const uint32_t*)(sm + D_SA_HI + aoff);
                aH[1] = *(const uint32_t*)(sm + D_SA_HI + aoff + 8*RPAD);
                aH[2] = *(const uint32_t*)(sm + D_SA_HI + aoff + 8);
                aH[3] = *(const uint32_t*)(sm + D_SA_HI + aoff + 8*RPAD + 8);
                aL[0] = *(const uint32_t*)(sm + D_SA_LO + aoff);
                aL[1] = *(const uint32_t*)(sm + D_SA_LO + aoff + 8*RPAD);
                aL[2] = *(const uint32_t*)(sm + D_SA_LO + aoff + 8);
                aL[3] = *(const uint32_t*)(sm + D_SA_LO + aoff + 8*RPAD + 8);
#pragma unroll
                for (int nt = 0; nt < 4; nt++) {
                    mma_bf16(cc[mt][nt], aH, &bH[nt*2]);
                    mma_bf16(cc[mt][nt], aH, &bL[nt*2]);
                    mma_bf16(cc[mt][nt], aL, &bH[nt*2]);
                }
            }
        }
        __syncthreads();
    }

    // epilogue: scatter-store fp32 pairs to out[token]
    const int qcol = (lane & 3) * 2;
#pragma unroll
    for (int mt = 0; mt < 2; mt++)
#pragma unroll
        for (int h = 0; h < 2; h++) {
            int rr = wm*32 + mt*16 + qrow + h*8;
            int tok = rowsS[rr];
            if (tok >= 0) {
                float* rowp = out + (size_t)tok * TH + n0;
#pragma unroll
                for (int nt = 0; nt < 4; nt++) {
                    float2 v = make_float2(cc[mt][nt][h*2+0], cc[mt][nt][h*2+1]);
                    *(float2*)(rowp + wn*32 + nt*8 + qcol) = v;
                }
            }
        }
}

// ================= launch =================
extern "C" void kernel_launch(void* const* d_in, const int* in_sizes, int n_in,
                              void* d_out, int out_size) {
    const float* x  = (const float*)d_in[0];   // [B,S,H]
    const float* gw = (const float*)d_in[1];   // [E,H]
    const float* wg = (const float*)d_in[2];   // [E,H,D]
    const float* wu = (const float*)d_in[3];   // [E,H,D]
    const float* wd = (const float*)d_in[4];   // [E,D,H]
    float* out = (float*)d_out;

    k_zero<<<1, 32>>>();
    k_router<<<TT/8, 256>>>(x, gw);
    k_scan<<<1, 32>>>();
    k_scatter<<<TT/256, 256>>>();
    {
        dim3 grid(TT/128, TD/64, TE);   // (128, 4, 8); idle tiles exit on count check
        k_upgate_mma<<<grid, 256>>>(x, wg, wu);
    }
    {
        dim3 grid(TT/128, TH/64, TE);   // (128, 16, 8)
        k_down_mma<<<grid, 256>>>(wd, out);
    }
}

// round 12
// speedup vs baseline: 1.9362x; 1.1130x over previous
#include <cuda_runtime.h>
#include <cuda_bf16.h>
#include <cstdint>

#define TB 4
#define TS 4096
#define TH 1024
#define TE 8
#define TD 256
#define TT (TB*TS)   // 16384 tokens

// ================= device scratch (static; proven in R10) =================
__device__ __align__(16) int   g_expert_of[TT];
__device__ __align__(16) int   g_count[TE];
__device__ __align__(16) int   g_offset[TE+1];
__device__ __align__(16) int   g_cursor[TE];
__device__ __align__(16) int   g_token_list[TT];
__device__ __align__(16) float g_inter[(size_t)TT*TD];   // 16MB, permuted-order rows, fp32

// ================= helpers =================
__device__ __forceinline__ void mma_bf16(float* c, const uint32_t* a, const uint32_t* b) {
    asm volatile("mma.sync.aligned.m16n8k16.row.col.f32.bf16.bf16.f32 "
                 "{%0,%1,%2,%3}, {%4,%5,%6,%7}, {%8,%9}, {%0,%1,%2,%3};"
                 : "+f"(c[0]), "+f"(c[1]), "+f"(c[2]), "+f"(c[3])
                 : "r"(a[0]), "r"(a[1]), "r"(a[2]), "r"(a[3]), "r"(b[0]), "r"(b[1]));
}
__device__ __forceinline__ void split_bf16(float v, __nv_bfloat16& h, __nv_bfloat16& l) {
    h = __float2bfloat16_rn(v);
    l = __float2bfloat16_rn(v - __bfloat162float(h));
}
#define RPAD 40   // bf16 elems per SMEM row (80B) -> conflict-free fragment LDS

// ================= kernel 0: zero =================
__global__ void k_zero() {
    int i = threadIdx.x;
    if (i < TE) { g_count[i] = 0; g_cursor[i] = 0; }
}

// ================= kernel 1: router =================
__global__ void k_router(const float* __restrict__ x, const float* __restrict__ gw) {
    __shared__ float sgw[TE*TH];
    for (int i = threadIdx.x; i < TE*TH; i += blockDim.x) sgw[i] = gw[i];
    __syncthreads();
    int warp = threadIdx.x >> 5, lane = threadIdx.x & 31;
    int t = blockIdx.x * 8 + warp;
    if (t >= TT) return;
    const float* xr = x + (size_t)t * TH;
    float acc[TE];
#pragma unroll
    for (int e = 0; e < TE; e++) acc[e] = 0.f;
#pragma unroll 4
    for (int i = 0; i < TH/32; i++) {
        float xv = xr[i*32 + lane];
#pragma unroll
        for (int e = 0; e < TE; e++) acc[e] += xv * sgw[e*TH + i*32 + lane];
    }
#pragma unroll
    for (int off = 16; off; off >>= 1)
#pragma unroll
        for (int e = 0; e < TE; e++) acc[e] += __shfl_xor_sync(0xFFFFFFFFu, acc[e], off);
    if (lane == 0) {
        int best = 0; float bv = acc[0];
#pragma unroll
        for (int e = 1; e < TE; e++) if (acc[e] > bv) { bv = acc[e]; best = e; }
        g_expert_of[t] = best;
        atomicAdd(&g_count[best], 1);
    }
}

// ================= kernel 2: scan =================
__global__ void k_scan() {
    if (threadIdx.x == 0) {
        int s = 0;
        for (int e = 0; e < TE; e++) { g_offset[e] = s; s += g_count[e]; }
        g_offset[TE] = s;
    }
}

// ================= kernel 3: scatter =================
__global__ void k_scatter() {
    int t = blockIdx.x * blockDim.x + threadIdx.x;
    if (t < TT) {
        int e = g_expert_of[t];
        int p = g_offset[e] + atomicAdd(&g_cursor[e], 1);
        g_token_list[p] = t;
    }
}

// ================= kernel 4: up+gate HMMA GEMM, register-prefetch pipeline =========
#define SA_HI 0
#define SA_LO (128*RPAD)
#define SBGH  (2*128*RPAD)
#define SBGL  (2*128*RPAD + 64*RPAD)
#define SBUH  (2*128*RPAD + 2*64*RPAD)
#define SBUL  (2*128*RPAD + 3*64*RPAD)
#define G1_ELEMS (2*128*RPAD + 4*64*RPAD)
__global__ __launch_bounds__(256, 1) void k_upgate_mma(const float* __restrict__ x,
                                                       const float* __restrict__ wg,
                                                       const float* __restrict__ wu) {
    __shared__ __align__(16) __nv_bfloat16 sm[G1_ELEMS];
    __shared__ int rowsS[128];
    const int tid = threadIdx.x, wid = tid >> 5, lane = tid & 31;
    const int e = blockIdx.z;
    const int off = g_offset[e];
    const int cnt = g_offset[e+1] - off;
    const int m0 = blockIdx.x * 128;
    if (m0 >= cnt) return;
    const int n0 = blockIdx.y * 64;
    const int valid = (cnt - m0 < 128) ? (cnt - m0) : 128;

    if (tid < 128) {
        int m = m0 + tid;
        rowsS[tid] = (m < cnt) ? g_token_list[off + m] : -1;
    }
    __syncthreads();

    const float* wge = wg + (size_t)e * TH * TD;
    const float* wue = wu + (size_t)e * TH * TD;

    // A loader: thread -> (row, half): 16 consecutive k each
    const int arow = tid >> 1, ahalf = tid & 1;
    int tokA = rowsS[arow];
    if (tokA < 0) tokA = rowsS[0];
    const float* asrc = x + (size_t)tokA * TH + ahalf * 16;
    // B loader: thread -> (n, 8 k values)
    const int bn = tid & 63, bk8 = (tid >> 6) * 8;

    float cG[2][4][4], cU[2][4][4];
#pragma unroll
    for (int a = 0; a < 2; a++)
#pragma unroll
        for (int b = 0; b < 4; b++)
#pragma unroll
            for (int c = 0; c < 4; c++) { cG[a][b][c] = 0.f; cU[a][b][c] = 0.f; }

    const int wm = wid & 3, wn = wid >> 2;
    const int qrow = lane >> 2, qk = (lane & 3) * 2;

    // prefetch registers
    float4 pa[4];
    float  pg[8], pu[8];
#define G1_LOAD_REGS(c) do {                                              \
        int _k0 = (c) * 32;                                               \
        _Pragma("unroll")                                                 \
        for (int j = 0; j < 4; j++) pa[j] = *(const float4*)(asrc + _k0 + j*4); \
        _Pragma("unroll")                                                 \
        for (int j = 0; j < 8; j++) pg[j] = wge[(size_t)(_k0 + bk8 + j) * TD + n0 + bn]; \
        _Pragma("unroll")                                                 \
        for (int j = 0; j < 8; j++) pu[j] = wue[(size_t)(_k0 + bk8 + j) * TD + n0 + bn]; \
    } while (0)

    const int NC = TH / 32;   // 32
    G1_LOAD_REGS(0);
    for (int c = 0; c < NC; c++) {
        __syncthreads();   // previous compute done reading SMEM
        // ---- convert + store chunk c from registers ----
        {
            __align__(16) __nv_bfloat16 hb[16], lb[16];
#pragma unroll
            for (int j = 0; j < 4; j++) {
                split_bf16(pa[j].x, hb[j*4+0], lb[j*4+0]);
                split_bf16(pa[j].y, hb[j*4+1], lb[j*4+1]);
                split_bf16(pa[j].z, hb[j*4+2], lb[j*4+2]);
                split_bf16(pa[j].w, hb[j*4+3], lb[j*4+3]);
            }
            uint32_t ao = arow*RPAD + ahalf*16;
            *(uint4*)(sm + SA_HI + ao)     = ((uint4*)hb)[0];
            *(uint4*)(sm + SA_HI + ao + 8) = ((uint4*)hb)[1];
            *(uint4*)(sm + SA_LO + ao)     = ((uint4*)lb)[0];
            *(uint4*)(sm + SA_LO + ao + 8) = ((uint4*)lb)[1];
#pragma unroll
            for (int j = 0; j < 8; j++) split_bf16(pg[j], hb[j], lb[j]);
            *(uint4*)(sm + SBGH + bn*RPAD + bk8) = *(uint4*)hb;
            *(uint4*)(sm + SBGL + bn*RPAD + bk8) = *(uint4*)lb;
#pragma unroll
            for (int j = 0; j < 8; j++) split_bf16(pu[j], hb[j], lb[j]);
            *(uint4*)(sm + SBUH + bn*RPAD + bk8) = *(uint4*)hb;
            *(uint4*)(sm + SBUL + bn*RPAD + bk8) = *(uint4*)lb;
        }
        __syncthreads();   // stores visible
        if (c + 1 < NC) G1_LOAD_REGS(c + 1);   // overlap LDG with compute below
        // ---- compute chunk c ----
#pragma unroll
        for (int ks = 0; ks < 2; ks++) {
            uint32_t bGh[8], bGl[8], bUh[8], bUl[8];
#pragma unroll
            for (int nt = 0; nt < 4; nt++) {
                int boff = (wn*32 + nt*8 + qrow)*RPAD + ks*16 + qk;
                bGh[nt*2+0] = *(const uint32_t*)(sm + SBGH + boff);
                bGh[nt*2+1] = *(const uint32_t*)(sm + SBGH + boff + 8);
                bGl[nt*2+0] = *(const uint32_t*)(sm + SBGL + boff);
                bGl[nt*2+1] = *(const uint32_t*)(sm + SBGL + boff + 8);
                bUh[nt*2+0] = *(const uint32_t*)(sm + SBUH + boff);
                bUh[nt*2+1] = *(const uint32_t*)(sm + SBUH + boff + 8);
                bUl[nt*2+0] = *(const uint32_t*)(sm + SBUL + boff);
                bUl[nt*2+1] = *(const uint32_t*)(sm + SBUL + boff + 8);
            }
#pragma unroll
            for (int mt = 0; mt < 2; mt++) {
                int aoff = (wm*32 + mt*16 + qrow)*RPAD + ks*16 + qk;
                uint32_t aH[4], aL[4];
                aH[0] = *(const uint32_t*)(sm + SA_HI + aoff);
                aH[1] = *(const uint32_t*)(sm + SA_HI + aoff + 8*RPAD);
                aH[2] = *(const uint32_t*)(sm + SA_HI + aoff + 8);
                aH[3] = *(const uint32_t*)(sm + SA_HI + aoff + 8*RPAD + 8);
                aL[0] = *(const uint32_t*)(sm + SA_LO + aoff);
                aL[1] = *(const uint32_t*)(sm + SA_LO + aoff + 8*RPAD);
                aL[2] = *(const uint32_t*)(sm + SA_LO + aoff + 8);
                aL[3] = *(const uint32_t*)(sm + SA_LO + aoff + 8*RPAD + 8);
#pragma unroll
                for (int nt = 0; nt < 4; nt++) {
                    mma_bf16(cG[mt][nt], aH, &bGh[nt*2]);
                    mma_bf16(cG[mt][nt], aH, &bGl[nt*2]);
                    mma_bf16(cG[mt][nt], aL, &bGh[nt*2]);
                    mma_bf16(cU[mt][nt], aH, &bUh[nt*2]);
                    mma_bf16(cU[mt][nt], aH, &bUl[nt*2]);
                    mma_bf16(cU[mt][nt], aL, &bUh[nt*2]);
                }
            }
        }
    }

    // epilogue: inter = relu(g)^2 * u, fp32 store to permuted rows
    const int qcol = (lane & 3) * 2;
#pragma unroll
    for (int mt = 0; mt < 2; mt++)
#pragma unroll
        for (int h = 0; h < 2; h++) {
            int rr = wm*32 + mt*16 + qrow + h*8;
            if (rr < valid) {
                float* rowp = g_inter + (size_t)(off + m0 + rr) * TD + n0;
#pragma unroll
                for (int nt = 0; nt < 4; nt++) {
                    float g0 = fmaxf(cG[mt][nt][h*2+0], 0.f);
                    float g1 = fmaxf(cG[mt][nt][h*2+1], 0.f);
                    float2 v = make_float2(g0*g0*cU[mt][nt][h*2+0],
                                           g1*g1*cU[mt][nt][h*2+1]);
                    *(float2*)(rowp + wn*32 + nt*8 + qcol) = v;
                }
            }
        }
}

// ================= kernel 5: down-proj HMMA GEMM + scatter store, pipelined =========
#define D_SA_HI 0
#define D_SA_LO (128*RPAD)
#define D_SBH   (2*128*RPAD)
#define D_SBL   (2*128*RPAD + 64*RPAD)
#define G2_ELEMS (2*128*RPAD + 2*64*RPAD)
__global__ __launch_bounds__(256, 1) void k_down_mma(const float* __restrict__ wd,
                                                     float* __restrict__ out) {
    __shared__ __align__(16) __nv_bfloat16 sm[G2_ELEMS];
    __shared__ int rowsS[128];
    const int tid = threadIdx.x, wid = tid >> 5, lane = tid & 31;
    const int e = blockIdx.z;
    const int off = g_offset[e];
    const int cnt = g_offset[e+1] - off;
    const int m0 = blockIdx.x * 128;
    if (m0 >= cnt) return;
    const int n0 = blockIdx.y * 64;
    const int valid = (cnt - m0 < 128) ? (cnt - m0) : 128;

    if (tid < 128) {
        int m = m0 + tid;
        rowsS[tid] = (m < cnt) ? g_token_list[off + m] : -1;
    }
    __syncthreads();

    const float* wde = wd + (size_t)e * TD * TH;

    const int arow = tid >> 1, ahalf = tid & 1;
    const int arowc = (arow < valid) ? arow : (valid - 1);
    const float* asrc = g_inter + (size_t)(off + m0 + arowc) * TD + ahalf * 16;
    const int bn = tid & 63, bk8 = (tid >> 6) * 8;

    float cc[2][4][4];
#pragma unroll
    for (int a = 0; a < 2; a++)
#pragma unroll
        for (int b = 0; b < 4; b++)
#pragma unroll
            for (int c = 0; c < 4; c++) cc[a][b][c] = 0.f;

    const int wm = wid & 3, wn = wid >> 2;
    const int qrow = lane >> 2, qk = (lane & 3) * 2;

    float4 pa[4];
    float  pb[8];
#define G2_LOAD_REGS(c) do {                                              \
        int _k0 = (c) * 32;                                               \
        _Pragma("unroll")                                                 \
        for (int j = 0; j < 4; j++) pa[j] = *(const float4*)(asrc + _k0 + j*4); \
        _Pragma("unroll")                                                 \
        for (int j = 0; j < 8; j++) pb[j] = wde[(size_t)(_k0 + bk8 + j) * TH + n0 + bn]; \
    } while (0)

    const int NC = TD / 32;   // 8
    G2_LOAD_REGS(0);
    for (int c = 0; c < NC; c++) {
        __syncthreads();
        {
            __align__(16) __nv_bfloat16 hb[16], lb[16];
#pragma unroll
            for (int j = 0; j < 4; j++) {
                split_bf16(pa[j].x, hb[j*4+0], lb[j*4+0]);
                split_bf16(pa[j].y, hb[j*4+1], lb[j*4+1]);
                split_bf16(pa[j].z, hb[j*4+2], lb[j*4+2]);
                split_bf16(pa[j].w, hb[j*4+3], lb[j*4+3]);
            }
            uint32_t ao = arow*RPAD + ahalf*16;
            *(uint4*)(sm + D_SA_HI + ao)     = ((uint4*)hb)[0];
            *(uint4*)(sm + D_SA_HI + ao + 8) = ((uint4*)hb)[1];
            *(uint4*)(sm + D_SA_LO + ao)     = ((uint4*)lb)[0];
            *(uint4*)(sm + D_SA_LO + ao + 8) = ((uint4*)lb)[1];
#pragma unroll
            for (int j = 0; j < 8; j++) split_bf16(pb[j], hb[j], lb[j]);
            *(uint4*)(sm + D_SBH + bn*RPAD + bk8) = *(uint4*)hb;
            *(uint4*)(sm + D_SBL + bn*RPAD + bk8) = *(uint4*)lb;
        }
        __syncthreads();
        if (c + 1 < NC) G2_LOAD_REGS(c + 1);
#pragma unroll
        for (int ks = 0; ks < 2; ks++) {
            uint32_t bH[8], bL[8];
#pragma unroll
            for (int nt = 0; nt < 4; nt++) {
                int boff = (wn*32 + nt*8 + qrow)*RPAD + ks*16 + qk;
                bH[nt*2+0] = *(const uint32_t*)(sm + D_SBH + boff);
                bH[nt*2+1] = *(const uint32_t*)(sm + D_SBH + boff + 8);
                bL[nt*2+0] = *(const uint32_t*)(sm + D_SBL + boff);
                bL[nt*2+1] = *(const uint32_t*)(sm + D_SBL + boff + 8);
            }
#pragma unroll
            for (int mt = 0; mt < 2; mt++) {
                int aoff = (wm*32 + mt*16 + qrow)*RPAD + ks*16 + qk;
                uint32_t aH[4], aL[4];
                aH[0] = *(const uint32_t*)(sm + D_SA_HI + aoff);
                aH[1] = *(const uint32_t*)(sm + D_SA_HI + aoff + 8*RPAD);
                aH[2] = *(const uint32_t*)(sm + D_SA_HI + aoff + 8);
                aH[3] = *(const uint32_t*)(sm + D_SA_HI + aoff + 8*RPAD + 8);
                aL[0] = *(const uint32_t*)(sm + D_SA_LO + aoff);
                aL[1] = *(const uint32_t*)(sm + D_SA_LO + aoff + 8*RPAD);
                aL[2] = *(const uint32_t*)(sm + D_SA_LO + aoff + 8);
                aL[3] = *(const uint32_t*)(sm + D_SA_LO + aoff + 8*RPAD + 8);
#pragma unroll
                for (int nt = 0; nt < 4; nt++) {
                    mma_bf16(cc[mt][nt], aH, &bH[nt*2]);
                    mma_bf16(cc[mt][nt], aH, &bL[nt*2]);
                    mma_bf16(cc[mt][nt], aL, &bH[nt*2]);
                }
            }
        }
    }

    // epilogue: scatter-store fp32 pairs to out[token]
    const int qcol = (lane & 3) * 2;
#pragma unroll
    for (int mt = 0; mt < 2; mt++)
#pragma unroll
        for (int h = 0; h < 2; h++) {
            int rr = wm*32 + mt*16 + qrow + h*8;
            int tok = rowsS[rr];
            if (tok >= 0) {
                float* rowp = out + (size_t)tok * TH + n0;
#pragma unroll
                for (int nt = 0; nt < 4; nt++) {
                    float2 v = make_float2(cc[mt][nt][h*2+0], cc[mt][nt][h*2+1]);
                    *(float2*)(rowp + wn*32 + nt*8 + qcol) = v;
                }
            }
        }
}

// ================= launch =================
extern "C" void kernel_launch(void* const* d_in, const int* in_sizes, int n_in,
                              void* d_out, int out_size) {
    const float* x  = (const float*)d_in[0];   // [B,S,H]
    const float* gw = (const float*)d_in[1];   // [E,H]
    const float* wg = (const float*)d_in[2];   // [E,H,D]
    const float* wu = (const float*)d_in[3];   // [E,H,D]
    const float* wd = (const float*)d_in[4];   // [E,D,H]
    float* out = (float*)d_out;

    k_zero<<<1, 32>>>();
    k_router<<<TT/8, 256>>>(x, gw);
    k_scan<<<1, 32>>>();
    k_scatter<<<TT/256, 256>>>();
    {
        dim3 grid(TT/128, TD/64, TE);   // (128, 4, 8); idle tiles exit on count check
        k_upgate_mma<<<grid, 256>>>(x, wg, wu);
    }
    {
        dim3 grid(TT/128, TH/64, TE);   // (128, 16, 8)
        k_down_mma<<<grid, 256>>>(wd, out);
    }
}